// round 3
// baseline (speedup 1.0000x reference)
#include <cuda_runtime.h>
#include <cuda_fp8.h>
#include <cstdint>

// ============================ problem dims ============================
#define MSZ 16384
#define NSZ 2048
#define KSZ 2048

// ============================ GEMM config =============================
#define BM 256
#define BN 128
#define BK 64
#define KT (KSZ / BK)            // 32 k-tiles
#define STAGES 4
#define ASTRIDE 80               // bytes per smem row (64 data + 16 pad) -> conflict-free
#define A_SMEM_BYTES (BM * ASTRIDE)   // 20480
#define B_SMEM_BYTES (BN * ASTRIDE)   // 10240
#define STAGE_BYTES (A_SMEM_BYTES + B_SMEM_BYTES)   // 30720
#define SMEM_TOTAL (STAGES * STAGE_BYTES)           // 122880

// ============================ scratch =================================
__device__ __align__(1024) uint8_t g_xq[(size_t)MSZ * KSZ];
__device__ __align__(1024) uint8_t g_wq[(size_t)NSZ * KSZ];
__device__ float g_amax[2];

// ============================ PTX helpers =============================
__device__ __forceinline__ uint32_t smem_u32(const void* p) {
    uint32_t a;
    asm("{ .reg .u64 t; cvta.to.shared.u64 t, %1; cvt.u32.u64 %0, t; }"
        : "=r"(a) : "l"(p));
    return a;
}

__device__ __forceinline__ void cp_async16(uint32_t dst, const void* src) {
    asm volatile("cp.async.cg.shared.global [%0], [%1], 16;"
                 :: "r"(dst), "l"(src) : "memory");
}
#define CP_COMMIT() asm volatile("cp.async.commit_group;" ::: "memory")
#define CP_WAIT(n)  asm volatile("cp.async.wait_group %0;" :: "n"(n) : "memory")

__device__ __forceinline__ uint32_t lds32(uint32_t addr) {
    uint32_t v;
    asm volatile("ld.shared.b32 %0, [%1];" : "=r"(v) : "r"(addr));
    return v;
}

__device__ __forceinline__ void mma_e4m3(float d[4], const uint32_t a[4],
                                         const uint32_t b[2]) {
    asm volatile(
        "mma.sync.aligned.m16n8k32.row.col.f32.e4m3.e4m3.f32 "
        "{%0,%1,%2,%3}, {%4,%5,%6,%7}, {%8,%9}, {%0,%1,%2,%3};"
        : "+f"(d[0]), "+f"(d[1]), "+f"(d[2]), "+f"(d[3])
        : "r"(a[0]), "r"(a[1]), "r"(a[2]), "r"(a[3]),
          "r"(b[0]), "r"(b[1]));
}

// ============================ quant kernels ===========================

__global__ void zero_amax_kernel() {
    if (threadIdx.x < 2) g_amax[threadIdx.x] = 0.0f;
}

// x [M,K] f32 -> g_xq [M,K] e4m3 (scaled by scale[0]); amax(|x|) -> g_amax[0]
__global__ void quant_x_kernel(const float* __restrict__ x,
                               const float* __restrict__ scale) {
    const float s = __ldg(&scale[0]);
    const int n4 = (MSZ * KSZ) / 4;
    const int stride = gridDim.x * blockDim.x;
    const float4* x4 = (const float4*)x;
    uint32_t* q4 = (uint32_t*)g_xq;
    float amax = 0.0f;
    for (int i = blockIdx.x * blockDim.x + threadIdx.x; i < n4; i += stride) {
        float4 v = x4[i];
        amax = fmaxf(amax, fmaxf(fmaxf(fabsf(v.x), fabsf(v.y)),
                                 fmaxf(fabsf(v.z), fabsf(v.w))));
        uint32_t lo = __nv_cvt_float2_to_fp8x2(make_float2(v.x * s, v.y * s),
                                               __NV_SATFINITE, __NV_E4M3);
        uint32_t hi = __nv_cvt_float2_to_fp8x2(make_float2(v.z * s, v.w * s),
                                               __NV_SATFINITE, __NV_E4M3);
        q4[i] = lo | (hi << 16);
    }
    #pragma unroll
    for (int o = 16; o; o >>= 1)
        amax = fmaxf(amax, __shfl_xor_sync(0xFFFFFFFFu, amax, o));
    __shared__ float wmax[8];
    if ((threadIdx.x & 31) == 0) wmax[threadIdx.x >> 5] = amax;
    __syncthreads();
    if (threadIdx.x == 0) {
        float m = wmax[0];
        #pragma unroll
        for (int i = 1; i < 8; i++) m = fmaxf(m, wmax[i]);
        atomicMax((int*)&g_amax[0], __float_as_int(m));
    }
}

// kernel [K,N] f32 -> g_wq [N,K] e4m3 (transpose, scaled by scale[1]); amax -> g_amax[1]
__global__ void quant_w_kernel(const float* __restrict__ w,
                               const float* __restrict__ scale) {
    __shared__ float tile[32][33];
    const float s = __ldg(&scale[1]);
    const int k0 = blockIdx.y * 32, n0 = blockIdx.x * 32;
    const int tx = threadIdx.x, ty = threadIdx.y;   // block (8, 32)
    const int t = ty * 8 + tx;                      // 0..255
    float amax = 0.0f;
    #pragma unroll
    for (int it = 0; it < 4; it++) {
        int e = it * 256 + t;
        int kk = e >> 5, nn = e & 31;
        float v = w[(size_t)(k0 + kk) * NSZ + n0 + nn];
        amax = fmaxf(amax, fabsf(v));
        tile[kk][nn] = v;
    }
    __syncthreads();
    uint32_t u = 0;
    #pragma unroll
    for (int j = 0; j < 4; j++) {
        float v = tile[tx * 4 + j][ty] * s;
        uint32_t b = (uint32_t)__nv_cvt_float_to_fp8(v, __NV_SATFINITE, __NV_E4M3);
        u |= b << (8 * j);
    }
    *(uint32_t*)&g_wq[(size_t)(n0 + ty) * KSZ + k0 + tx * 4] = u;

    #pragma unroll
    for (int o = 16; o; o >>= 1)
        amax = fmaxf(amax, __shfl_xor_sync(0xFFFFFFFFu, amax, o));
    __shared__ float wmax[8];
    if ((t & 31) == 0) wmax[t >> 5] = amax;
    __syncthreads();
    if (t == 0) {
        float m = wmax[0];
        #pragma unroll
        for (int i = 1; i < 8; i++) m = fmaxf(m, wmax[i]);
        atomicMax((int*)&g_amax[1], __float_as_int(m));
    }
}

// faithful _sf_compute + rolled history (all zeros for H=1)
__global__ void scale_update_kernel(const float* __restrict__ scale,
                                    float* __restrict__ tail) {
    int i = threadIdx.x;
    if (i < 2) {
        float a = g_amax[i];
        float s = __ldg(&scale[i]);
        float e = floorf(log2f(448.0f / a));
        float sf = rintf(exp2f(fabsf(e)));
        sf = (a > 0.0f) ? sf : s;
        sf = isinf(a) ? sf : s;
        sf = (e < 0.0f) ? (1.0f / sf) : sf;
        tail[i] = sf;          // new_scale
        tail[2 + i] = 0.0f;    // rolled amax_history
    }
}

// =========================== FP8 GEMM (mma.sync) =====================
// C[m0:m0+256, n0:n0+128] = A @ B^T, A = g_xq [M,K], B = g_wq [N,K].
// 512 threads = 16 warps in a 4x4 grid; warp tile 64x32.
__global__ void __launch_bounds__(512, 1) gemm_kernel(
    float* __restrict__ out, const float* __restrict__ scale)
{
    extern __shared__ char smem[];
    const uint32_t sb = smem_u32(smem);
    const int tid = threadIdx.x, wid = tid >> 5, lane = tid & 31;
    const int m0 = blockIdx.y * BM, n0 = blockIdx.x * BN;
    const int wm = (wid >> 2) * 64, wn = (wid & 3) * 32;
    const int lrow = lane >> 2;            // 0..7
    const int lkb = (lane & 3) * 4;        // byte offset in K

    // per-thread gmem/smem load coords (16B chunks)
    const int ldrow = tid >> 2;            // 0..127
    const int ldchk = (tid & 3) * 16;      // 0/16/32/48

    const uint8_t* ag = g_xq + (size_t)(m0 + ldrow) * KSZ + ldchk;
    const uint8_t* bg = g_wq + (size_t)(n0 + ldrow) * KSZ + ldchk;
    const uint32_t adst = sb + ldrow * ASTRIDE + ldchk;
    const uint32_t bdst = sb + A_SMEM_BYTES + ldrow * ASTRIDE + ldchk;

    float acc[4][4][4] = {};

    // ---- prologue: fill 3 stages ----
    #pragma unroll
    for (int s = 0; s < STAGES - 1; s++) {
        const uint32_t so = s * STAGE_BYTES;
        const int k0 = s * BK;
        cp_async16(adst + so, ag + k0);
        cp_async16(adst + so + 128 * ASTRIDE, ag + k0 + (size_t)128 * KSZ);
        cp_async16(bdst + so, bg + k0);
        CP_COMMIT();
    }

    for (int it = 0; it < KT; it++) {
        const int s = it & (STAGES - 1);
        const uint32_t so = s * STAGE_BYTES;
        CP_WAIT(STAGES - 2);
        __syncthreads();

        // issue loads for stage it+3 (overwrites stage computed at it-1)
        const int nxt = it + STAGES - 1;
        if (nxt < KT) {
            const uint32_t no = (nxt & (STAGES - 1)) * STAGE_BYTES;
            const int k0 = nxt * BK;
            cp_async16(adst + no, ag + k0);
            cp_async16(adst + no + 128 * ASTRIDE, ag + k0 + (size_t)128 * KSZ);
            cp_async16(bdst + no, bg + k0);
        }
        CP_COMMIT();

        // ---- compute stage s: 2 k-steps of 32 ----
        const uint32_t as = sb + so;
        const uint32_t bs = as + A_SMEM_BYTES;
        #pragma unroll
        for (int ks = 0; ks < 2; ks++) {
            const int kb = ks * 32 + lkb;
            uint32_t afr[4][4];
            #pragma unroll
            for (int mt = 0; mt < 4; mt++) {
                const uint32_t r0 = as + (wm + mt * 16 + lrow) * ASTRIDE + kb;
                afr[mt][0] = lds32(r0);
                afr[mt][1] = lds32(r0 + 8 * ASTRIDE);
                afr[mt][2] = lds32(r0 + 16);
                afr[mt][3] = lds32(r0 + 8 * ASTRIDE + 16);
            }
            uint32_t bfr[4][2];
            #pragma unroll
            for (int nt = 0; nt < 4; nt++) {
                const uint32_t r0 = bs + (wn + nt * 8 + lrow) * ASTRIDE + kb;
                bfr[nt][0] = lds32(r0);
                bfr[nt][1] = lds32(r0 + 16);
            }
            #pragma unroll
            for (int mt = 0; mt < 4; mt++)
                #pragma unroll
                for (int nt = 0; nt < 4; nt++)
                    mma_e4m3(acc[mt][nt], afr[mt], bfr[nt]);
        }
    }

    // ---- epilogue ----
    const float inv = (1.0f / __ldg(&scale[0])) * (1.0f / __ldg(&scale[1]));
    #pragma unroll
    for (int mt = 0; mt < 4; mt++) {
        const int row = m0 + wm + mt * 16 + lrow;
        #pragma unroll
        for (int nt = 0; nt < 4; nt++) {
            const int col = n0 + wn + nt * 8 + (lane & 3) * 2;
            float2 v0 = make_float2(acc[mt][nt][0] * inv, acc[mt][nt][1] * inv);
            float2 v1 = make_float2(acc[mt][nt][2] * inv, acc[mt][nt][3] * inv);
            *(float2*)&out[(size_t)row * NSZ + col] = v0;
            *(float2*)&out[(size_t)(row + 8) * NSZ + col] = v1;
        }
    }
}

// ============================ host launch =============================
extern "C" void kernel_launch(void* const* d_in, const int* in_sizes, int n_in,
                              void* d_out, int out_size) {
    const float* x     = (const float*)d_in[0];
    const float* w     = (const float*)d_in[1];
    const float* scale = (const float*)d_in[2];
    float* out = (float*)d_out;

    zero_amax_kernel<<<1, 32>>>();
    quant_x_kernel<<<1184, 256>>>(x, scale);
    quant_w_kernel<<<dim3(NSZ / 32, KSZ / 32), dim3(8, 32)>>>(w, scale);
    scale_update_kernel<<<1, 32>>>(scale, out + (out_size - 4));

    static bool attr_set = false;
    if (!attr_set) {
        cudaFuncSetAttribute(gemm_kernel,
                             cudaFuncAttributeMaxDynamicSharedMemorySize,
                             SMEM_TOTAL);
        attr_set = true;
    }
    gemm_kernel<<<dim3(NSZ / BN, MSZ / BM), 512, SMEM_TOTAL>>>(out, scale);
}